// round 7
// baseline (speedup 1.0000x reference)
#include <cuda_runtime.h>

// Problem constants (from reference setup_inputs)
#define T_DIM 16
#define B_DIM 32
#define N_DIM 196
#define C_DIM 512
#define TB_STRIDE (B_DIM * N_DIM * C_DIM)   // elements per timestep
#define SPIKES_ELEMS ((size_t)T_DIM * B_DIM * N_DIM * C_DIM)
#define NUM_UNITS 256                        // (b, 64-c-tile) work units
#define GRID_X 148                           // one block per SM

// FINAL. Block = 16 c-lanes (float4 -> 64 c) x 64 n-groups (1024 threads,
// one CTA per SM). Each thread carries 4 v-states: n = ny + 64k (k=3 valid
// only for ny<4; N=196=3*64+4). All of N lives in one block -> vpool
// reduction is block-local (parity-buffered, ONE barrier per timestep).
// 128-bit accesses; per k-slot the t+1 (or next-unit t=0) prefetch LDG
// issues just before the spike STG: loads (latency-critical) enter the LSU
// queue first, stores are fire-and-forget, and the chip sees a uniformly
// mixed R/W stream that minimizes DRAM turnaround. Reads stay outstanding
// across barriers and unit switches.
//
// Measured: 413MB irreducible traffic at ~6.1 TB/s effective = memory floor.
// Disproved: more blocks (R3), 2 CTAs/SM for barrier-skew tiling (R5).
__global__ __launch_bounds__(1024, 1)
void lif_dual_kernel(const float* __restrict__ x,
                     const float* __restrict__ decay,
                     float* __restrict__ spikes,
                     float* __restrict__ vpool) {
    const int cx   = threadIdx.x;        // 0..15  (c-lane, float4)
    const int ny   = threadIdx.y;        // 0..63  (n-group)
    const int flat = ny * 16 + cx;
    const int bid  = blockIdx.x;

    const float d = decay[0];
    const float inv_n = 1.0f / (float)N_DIM;
    const bool last_ok = (ny < (N_DIM - 3 * 64));   // ny < 4

    __shared__ float red[2][64][64];     // [parity][n-group][c]

    const int nu = (bid + GRID_X < NUM_UNITS) ? 2 : 1;

    // base(unit): b = unit>>3, ctile = unit&7; this thread: n = ny + 64k
    auto unit_base = [&](int unit) -> size_t {
        return ((size_t)(unit >> 3) * N_DIM + ny) * C_DIM + (unit & 7) * 64 + cx * 4;
    };

    // Prime the pipeline for the first unit (t=0 loads).
    float4 xv[4];
    {
        const size_t b0 = unit_base(bid);
#pragma unroll
        for (int k = 0; k < 3; k++)
            xv[k] = __ldcs(reinterpret_cast<const float4*>(x + b0 + (size_t)k * 64 * C_DIM));
        if (last_ok)
            xv[3] = __ldcs(reinterpret_cast<const float4*>(x + b0 + (size_t)3 * 64 * C_DIM));
    }

#pragma unroll 1
    for (int u = 0; u < nu; u++) {
        const int unit  = bid + u * GRID_X;
        const int ctile = unit & 7;
        const int b     = unit >> 3;
        const size_t base = unit_base(unit);

        float4 v[4];
#pragma unroll
        for (int k = 0; k < 4; k++) v[k] = make_float4(0.f, 0.f, 0.f, 0.f);

#pragma unroll 1
        for (int t = 0; t < T_DIM; t++) {
            const size_t off = base + (size_t)t * TB_STRIDE;
            const int par = t & 1;
            const bool more = (t < T_DIM - 1) || (u + 1 < nu);
            const size_t noff = (t < T_DIM - 1) ? (off + (size_t)TB_STRIDE)
                                                : unit_base(bid + GRID_X);

            float4 p = make_float4(0.f, 0.f, 0.f, 0.f);
#pragma unroll
            for (int k = 0; k < 4; k++) {
                if (k == 3 && !last_ok) break;
                const size_t ko = (size_t)k * 64 * C_DIM;
                float4 vv = v[k];
                vv.x = fmaf(d, vv.x, xv[k].x);
                vv.y = fmaf(d, vv.y, xv[k].y);
                vv.z = fmaf(d, vv.z, xv[k].z);
                vv.w = fmaf(d, vv.w, xv[k].w);
                // Prefetch for this slot (next t, or next unit's t=0) BEFORE
                // the store: xv[k] is now dead, load enters the queue first.
                if (more)
                    xv[k] = __ldcs(reinterpret_cast<const float4*>(x + noff + ko));
                p.x += vv.x; p.y += vv.y; p.z += vv.z; p.w += vv.w;   // pre-reset
                float4 s;
                s.x = (vv.x >= 1.0f) ? 1.0f : 0.0f;
                s.y = (vv.y >= 1.0f) ? 1.0f : 0.0f;
                s.z = (vv.z >= 1.0f) ? 1.0f : 0.0f;
                s.w = (vv.w >= 1.0f) ? 1.0f : 0.0f;
                __stcs(reinterpret_cast<float4*>(spikes + off + ko), s);
                vv.x = (s.x != 0.0f) ? 0.0f : vv.x;   // hard reset
                vv.y = (s.y != 0.0f) ? 0.0f : vv.y;
                vv.z = (s.z != 0.0f) ? 0.0f : vv.z;
                vv.w = (s.w != 0.0f) ? 0.0f : vv.w;
                v[k] = vv;
            }

            // Publish partial sums (STS.128, conflict-free).
            *reinterpret_cast<float4*>(&red[par][ny][4 * cx]) = p;

            __syncthreads();

            // 64 threads reduce 64 n-group partials for 64 c columns; hidden
            // under in-flight prefetch loads. One barrier is safe: the next
            // iteration writes the other parity buffer, and rewriting this
            // one requires these reducer threads to pass the next barrier.
            if (flat < 64) {
                float s = 0.0f;
#pragma unroll
                for (int j = 0; j < 64; j++) s += red[par][j][flat];
                vpool[((size_t)t * B_DIM + b) * C_DIM + ctile * 64 + flat] = s * inv_n;
            }
        }
        __syncthreads();   // unit boundary: red[] parity reuse + v reinit
    }
}

extern "C" void kernel_launch(void* const* d_in, const int* in_sizes, int n_in,
                              void* d_out, int out_size) {
    const float* x     = (const float*)d_in[0];
    const float* decay = (const float*)d_in[1];
    float* spikes = (float*)d_out;
    float* vpool  = (float*)d_out + SPIKES_ELEMS;

    dim3 grid(GRID_X, 1);
    dim3 block(16, 64);    // 16 c-lanes (float4) x 64 n-groups = 1024 threads
    lif_dual_kernel<<<grid, block>>>(x, decay, spikes, vpool);
}

// round 8
// speedup vs baseline: 1.4260x; 1.4260x over previous
#include <cuda_runtime.h>

// Problem constants (from reference setup_inputs)
#define T_DIM 16
#define B_DIM 32
#define N_DIM 196
#define C_DIM 512
#define TB_STRIDE (B_DIM * N_DIM * C_DIM)   // elements per timestep
#define SPIKES_ELEMS ((size_t)T_DIM * B_DIM * N_DIM * C_DIM)
#define NUM_UNITS 256                        // (b, 64-c-tile) work units
#define GRID_X 148                           // one block per SM

// FINAL (R4/R6 config — fastest measured, 68.06us / 6.07 TB/s effective).
// Block = 16 c-lanes (float4 -> 64 c) x 64 n-groups (1024 threads, one CTA
// per SM). Each thread carries 4 v-states: n = ny + 64k (k=3 valid only for
// ny<4; N=196=3*64+4). All of N lives in one block -> vpool reduction is
// block-local (parity-buffered, ONE barrier per timestep). 128-bit accesses;
// the t+1 (or next-unit t=0) prefetch LDG for slot k issues immediately
// AFTER slot k's spike STG — store first (fire-and-forget) then load into
// the now-dead xv[k]. NOTE (R7 lesson): swapping this order (LDG before STG)
// creates a WAR/scoreboard serialization on xv[k] that collapses MLP and
// costs +36us. Do not reorder.
//
// Measured: 413MB irreducible traffic at ~6.1 TB/s = mixed-R/W memory floor.
// Disproved: more blocks (R3), 2 CTAs/SM (R5), LDG-first interleave (R7).
__global__ __launch_bounds__(1024, 1)
void lif_dual_kernel(const float* __restrict__ x,
                     const float* __restrict__ decay,
                     float* __restrict__ spikes,
                     float* __restrict__ vpool) {
    const int cx   = threadIdx.x;        // 0..15  (c-lane, float4)
    const int ny   = threadIdx.y;        // 0..63  (n-group)
    const int flat = ny * 16 + cx;
    const int bid  = blockIdx.x;

    const float d = decay[0];
    const float inv_n = 1.0f / (float)N_DIM;
    const bool last_ok = (ny < (N_DIM - 3 * 64));   // ny < 4

    __shared__ float red[2][64][64];     // [parity][n-group][c]

    const int nu = (bid + GRID_X < NUM_UNITS) ? 2 : 1;

    // base(unit): b = unit>>3, ctile = unit&7; this thread: n = ny + 64k
    auto unit_base = [&](int unit) -> size_t {
        return ((size_t)(unit >> 3) * N_DIM + ny) * C_DIM + (unit & 7) * 64 + cx * 4;
    };

    // Prime the pipeline for the first unit (t=0 loads).
    float4 xv[4];
    {
        const size_t b0 = unit_base(bid);
#pragma unroll
        for (int k = 0; k < 3; k++)
            xv[k] = __ldcs(reinterpret_cast<const float4*>(x + b0 + (size_t)k * 64 * C_DIM));
        if (last_ok)
            xv[3] = __ldcs(reinterpret_cast<const float4*>(x + b0 + (size_t)3 * 64 * C_DIM));
    }

#pragma unroll 1
    for (int u = 0; u < nu; u++) {
        const int unit  = bid + u * GRID_X;
        const int ctile = unit & 7;
        const int b     = unit >> 3;
        const size_t base = unit_base(unit);

        float4 v[4];
#pragma unroll
        for (int k = 0; k < 4; k++) v[k] = make_float4(0.f, 0.f, 0.f, 0.f);

#pragma unroll 1
        for (int t = 0; t < T_DIM; t++) {
            const size_t off = base + (size_t)t * TB_STRIDE;
            const int par = t & 1;
            const bool more = (t < T_DIM - 1) || (u + 1 < nu);
            const size_t noff = (t < T_DIM - 1) ? (off + (size_t)TB_STRIDE)
                                                : unit_base(bid + GRID_X);

            float4 p = make_float4(0.f, 0.f, 0.f, 0.f);
#pragma unroll
            for (int k = 0; k < 4; k++) {
                if (k == 3 && !last_ok) break;
                const size_t ko = (size_t)k * 64 * C_DIM;
                float4 vv = v[k];
                vv.x = fmaf(d, vv.x, xv[k].x);
                vv.y = fmaf(d, vv.y, xv[k].y);
                vv.z = fmaf(d, vv.z, xv[k].z);
                vv.w = fmaf(d, vv.w, xv[k].w);
                p.x += vv.x; p.y += vv.y; p.z += vv.z; p.w += vv.w;   // pre-reset
                float4 s;
                s.x = (vv.x >= 1.0f) ? 1.0f : 0.0f;
                s.y = (vv.y >= 1.0f) ? 1.0f : 0.0f;
                s.z = (vv.z >= 1.0f) ? 1.0f : 0.0f;
                s.w = (vv.w >= 1.0f) ? 1.0f : 0.0f;
                __stcs(reinterpret_cast<float4*>(spikes + off + ko), s);
                vv.x = (s.x != 0.0f) ? 0.0f : vv.x;   // hard reset
                vv.y = (s.y != 0.0f) ? 0.0f : vv.y;
                vv.z = (s.z != 0.0f) ? 0.0f : vv.z;
                vv.w = (s.w != 0.0f) ? 0.0f : vv.w;
                v[k] = vv;
                // Interleaved prefetch for this slot (next t, or next unit
                // t=0), issued AFTER the store into the now-dead xv[k].
                if (more)
                    xv[k] = __ldcs(reinterpret_cast<const float4*>(x + noff + ko));
            }

            // Publish partial sums (STS.128, conflict-free).
            *reinterpret_cast<float4*>(&red[par][ny][4 * cx]) = p;

            __syncthreads();

            // 64 threads reduce 64 n-group partials for 64 c columns; hidden
            // under in-flight prefetch loads. One barrier is safe: the next
            // iteration writes the other parity buffer, and rewriting this
            // one requires these reducer threads to pass the next barrier.
            if (flat < 64) {
                float s = 0.0f;
#pragma unroll
                for (int j = 0; j < 64; j++) s += red[par][j][flat];
                vpool[((size_t)t * B_DIM + b) * C_DIM + ctile * 64 + flat] = s * inv_n;
            }
        }
        __syncthreads();   // unit boundary: red[] parity reuse + v reinit
    }
}

extern "C" void kernel_launch(void* const* d_in, const int* in_sizes, int n_in,
                              void* d_out, int out_size) {
    const float* x     = (const float*)d_in[0];
    const float* decay = (const float*)d_in[1];
    float* spikes = (float*)d_out;
    float* vpool  = (float*)d_out + SPIKES_ELEMS;

    dim3 grid(GRID_X, 1);
    dim3 block(16, 64);    // 16 c-lanes (float4) x 64 n-groups = 1024 threads
    lif_dual_kernel<<<grid, block>>>(x, decay, spikes, vpool);
}

// round 10
// speedup vs baseline: 1.5352x; 1.0766x over previous
#include <cuda_runtime.h>

// Problem constants (from reference setup_inputs)
#define T_DIM 16
#define B_DIM 32
#define N_DIM 196
#define C_DIM 512
#define TB_STRIDE (B_DIM * N_DIM * C_DIM)   // elements per timestep
#define SPIKES_ELEMS ((size_t)T_DIM * B_DIM * N_DIM * C_DIM)
#define NUM_UNITS 256                        // (b, 64-c-tile) work units
#define GRID_X 148                           // one block per SM

// FINAL (R4/R6 config — fastest measured: 68.06us, 4-run cluster 68.0-68.4).
// Block = 16 c-lanes (float4 -> 64 c) x 64 n-groups (1024 threads, one CTA
// per SM). Each thread carries 4 v-states: n = ny + 64k (k=3 valid only for
// ny<4; N=196=3*64+4). All of N lives in one block -> vpool reduction is
// block-local (parity-buffered, ONE barrier per timestep). 128-bit accesses;
// the t+1 (or next-unit t=0) prefetch LDG for slot k issues immediately
// AFTER slot k's spike STG — store first (fire-and-forget) then load into
// the now-dead xv[k]. NOTE (R7 lesson): swapping this order (LDG before STG)
// creates a WAR/scoreboard serialization on xv[k] that collapses MLP and
// costs +36us. Do not reorder.
//
// Measured: 413MB irreducible traffic at ~6.1 TB/s = mixed-R/W memory floor.
// Disproved: more blocks (R3), 2 CTAs/SM (R5), LDG-first interleave (R7).
// R8: byte-identical code measured 73.3us on a different board/clock state
// (DRAM% down, all SM-domain% up) -> +/-8% cross-session variance; do not
// tune against single anomalous sessions.
__global__ __launch_bounds__(1024, 1)
void lif_dual_kernel(const float* __restrict__ x,
                     const float* __restrict__ decay,
                     float* __restrict__ spikes,
                     float* __restrict__ vpool) {
    const int cx   = threadIdx.x;        // 0..15  (c-lane, float4)
    const int ny   = threadIdx.y;        // 0..63  (n-group)
    const int flat = ny * 16 + cx;
    const int bid  = blockIdx.x;

    const float d = decay[0];
    const float inv_n = 1.0f / (float)N_DIM;
    const bool last_ok = (ny < (N_DIM - 3 * 64));   // ny < 4

    __shared__ float red[2][64][64];     // [parity][n-group][c]

    const int nu = (bid + GRID_X < NUM_UNITS) ? 2 : 1;

    // base(unit): b = unit>>3, ctile = unit&7; this thread: n = ny + 64k
    auto unit_base = [&](int unit) -> size_t {
        return ((size_t)(unit >> 3) * N_DIM + ny) * C_DIM + (unit & 7) * 64 + cx * 4;
    };

    // Prime the pipeline for the first unit (t=0 loads).
    float4 xv[4];
    {
        const size_t b0 = unit_base(bid);
#pragma unroll
        for (int k = 0; k < 3; k++)
            xv[k] = __ldcs(reinterpret_cast<const float4*>(x + b0 + (size_t)k * 64 * C_DIM));
        if (last_ok)
            xv[3] = __ldcs(reinterpret_cast<const float4*>(x + b0 + (size_t)3 * 64 * C_DIM));
    }

#pragma unroll 1
    for (int u = 0; u < nu; u++) {
        const int unit  = bid + u * GRID_X;
        const int ctile = unit & 7;
        const int b     = unit >> 3;
        const size_t base = unit_base(unit);

        float4 v[4];
#pragma unroll
        for (int k = 0; k < 4; k++) v[k] = make_float4(0.f, 0.f, 0.f, 0.f);

#pragma unroll 1
        for (int t = 0; t < T_DIM; t++) {
            const size_t off = base + (size_t)t * TB_STRIDE;
            const int par = t & 1;
            const bool more = (t < T_DIM - 1) || (u + 1 < nu);
            const size_t noff = (t < T_DIM - 1) ? (off + (size_t)TB_STRIDE)
                                                : unit_base(bid + GRID_X);

            float4 p = make_float4(0.f, 0.f, 0.f, 0.f);
#pragma unroll
            for (int k = 0; k < 4; k++) {
                if (k == 3 && !last_ok) break;
                const size_t ko = (size_t)k * 64 * C_DIM;
                float4 vv = v[k];
                vv.x = fmaf(d, vv.x, xv[k].x);
                vv.y = fmaf(d, vv.y, xv[k].y);
                vv.z = fmaf(d, vv.z, xv[k].z);
                vv.w = fmaf(d, vv.w, xv[k].w);
                p.x += vv.x; p.y += vv.y; p.z += vv.z; p.w += vv.w;   // pre-reset
                float4 s;
                s.x = (vv.x >= 1.0f) ? 1.0f : 0.0f;
                s.y = (vv.y >= 1.0f) ? 1.0f : 0.0f;
                s.z = (vv.z >= 1.0f) ? 1.0f : 0.0f;
                s.w = (vv.w >= 1.0f) ? 1.0f : 0.0f;
                __stcs(reinterpret_cast<float4*>(spikes + off + ko), s);
                vv.x = (s.x != 0.0f) ? 0.0f : vv.x;   // hard reset
                vv.y = (s.y != 0.0f) ? 0.0f : vv.y;
                vv.z = (s.z != 0.0f) ? 0.0f : vv.z;
                vv.w = (s.w != 0.0f) ? 0.0f : vv.w;
                v[k] = vv;
                // Interleaved prefetch for this slot (next t, or next unit
                // t=0), issued AFTER the store into the now-dead xv[k].
                if (more)
                    xv[k] = __ldcs(reinterpret_cast<const float4*>(x + noff + ko));
            }

            // Publish partial sums (STS.128, conflict-free).
            *reinterpret_cast<float4*>(&red[par][ny][4 * cx]) = p;

            __syncthreads();

            // 64 threads reduce 64 n-group partials for 64 c columns; hidden
            // under in-flight prefetch loads. One barrier is safe: the next
            // iteration writes the other parity buffer, and rewriting this
            // one requires these reducer threads to pass the next barrier.
            if (flat < 64) {
                float s = 0.0f;
#pragma unroll
                for (int j = 0; j < 64; j++) s += red[par][j][flat];
                vpool[((size_t)t * B_DIM + b) * C_DIM + ctile * 64 + flat] = s * inv_n;
            }
        }
        __syncthreads();   // unit boundary: red[] parity reuse + v reinit
    }
}

extern "C" void kernel_launch(void* const* d_in, const int* in_sizes, int n_in,
                              void* d_out, int out_size) {
    const float* x     = (const float*)d_in[0];
    const float* decay = (const float*)d_in[1];
    float* spikes = (float*)d_out;
    float* vpool  = (float*)d_out + SPIKES_ELEMS;

    dim3 grid(GRID_X, 1);
    dim3 block(16, 64);    // 16 c-lanes (float4) x 64 n-groups = 1024 threads
    lif_dual_kernel<<<grid, block>>>(x, decay, spikes, vpool);
}

// round 12
// speedup vs baseline: 1.5454x; 1.0066x over previous
#include <cuda_runtime.h>

// Problem constants (from reference setup_inputs)
#define T_DIM 16
#define B_DIM 32
#define N_DIM 196
#define C_DIM 512
#define TB_STRIDE (B_DIM * N_DIM * C_DIM)   // elements per timestep
#define SPIKES_ELEMS ((size_t)T_DIM * B_DIM * N_DIM * C_DIM)
#define NUM_UNITS 256                        // (b, 64-c-tile) work units
#define GRID_X 148                           // one block per SM

// FINAL — converged at the memory-bound floor.
// Measurements for this exact source: 68.06 / 68.06 / 73.31(board outlier) /
// 68.10 us. Kernel-level: 60.8us = 6.8 TB/s on 413MB irreducible traffic,
// at the B300 LTS ceiling for a 50/50 R/W mix (DRAM-active 72-75% across
// every structural variant = controller turnaround, not exposed latency).
//
// Design: Block = 16 c-lanes (float4 -> 64 c) x 64 n-groups (1024 threads,
// one CTA per SM). Each thread carries 4 v-states: n = ny + 64k (k=3 valid
// only for ny<4; N=196=3*64+4). All of N in one block -> vpool reduction is
// block-local, parity double-buffered, ONE barrier per timestep, hidden
// under in-flight prefetch loads. Per k-slot the t+1 (or next-unit t=0)
// prefetch LDG issues immediately AFTER the spike STG into the now-dead
// xv[k]: uniform mixed R/W stream, reads always outstanding across barriers
// and the unit switch.
//
// Verified wins: cross-barrier prefetch + 1-barrier reduction (-7.8us);
// float4 + STG-then-LDG interleave (-2.8us kernel).
// Disproved: grid=148 vs 128 (neutral), 2x512 CTAs/SM (+2.5us),
// LDG-before-STG (+36us — WAR/scoreboard serialization on xv[k]; do NOT
// reorder), single-session anomalies (R8: +5us on identical binary).
__global__ __launch_bounds__(1024, 1)
void lif_dual_kernel(const float* __restrict__ x,
                     const float* __restrict__ decay,
                     float* __restrict__ spikes,
                     float* __restrict__ vpool) {
    const int cx   = threadIdx.x;        // 0..15  (c-lane, float4)
    const int ny   = threadIdx.y;        // 0..63  (n-group)
    const int flat = ny * 16 + cx;
    const int bid  = blockIdx.x;

    const float d = decay[0];
    const float inv_n = 1.0f / (float)N_DIM;
    const bool last_ok = (ny < (N_DIM - 3 * 64));   // ny < 4

    __shared__ float red[2][64][64];     // [parity][n-group][c]

    const int nu = (bid + GRID_X < NUM_UNITS) ? 2 : 1;

    // base(unit): b = unit>>3, ctile = unit&7; this thread: n = ny + 64k
    auto unit_base = [&](int unit) -> size_t {
        return ((size_t)(unit >> 3) * N_DIM + ny) * C_DIM + (unit & 7) * 64 + cx * 4;
    };

    // Prime the pipeline for the first unit (t=0 loads).
    float4 xv[4];
    {
        const size_t b0 = unit_base(bid);
#pragma unroll
        for (int k = 0; k < 3; k++)
            xv[k] = __ldcs(reinterpret_cast<const float4*>(x + b0 + (size_t)k * 64 * C_DIM));
        if (last_ok)
            xv[3] = __ldcs(reinterpret_cast<const float4*>(x + b0 + (size_t)3 * 64 * C_DIM));
    }

#pragma unroll 1
    for (int u = 0; u < nu; u++) {
        const int unit  = bid + u * GRID_X;
        const int ctile = unit & 7;
        const int b     = unit >> 3;
        const size_t base = unit_base(unit);

        float4 v[4];
#pragma unroll
        for (int k = 0; k < 4; k++) v[k] = make_float4(0.f, 0.f, 0.f, 0.f);

#pragma unroll 1
        for (int t = 0; t < T_DIM; t++) {
            const size_t off = base + (size_t)t * TB_STRIDE;
            const int par = t & 1;
            const bool more = (t < T_DIM - 1) || (u + 1 < nu);
            const size_t noff = (t < T_DIM - 1) ? (off + (size_t)TB_STRIDE)
                                                : unit_base(bid + GRID_X);

            float4 p = make_float4(0.f, 0.f, 0.f, 0.f);
#pragma unroll
            for (int k = 0; k < 4; k++) {
                if (k == 3 && !last_ok) break;
                const size_t ko = (size_t)k * 64 * C_DIM;
                float4 vv = v[k];
                vv.x = fmaf(d, vv.x, xv[k].x);
                vv.y = fmaf(d, vv.y, xv[k].y);
                vv.z = fmaf(d, vv.z, xv[k].z);
                vv.w = fmaf(d, vv.w, xv[k].w);
                p.x += vv.x; p.y += vv.y; p.z += vv.z; p.w += vv.w;   // pre-reset
                float4 s;
                s.x = (vv.x >= 1.0f) ? 1.0f : 0.0f;
                s.y = (vv.y >= 1.0f) ? 1.0f : 0.0f;
                s.z = (vv.z >= 1.0f) ? 1.0f : 0.0f;
                s.w = (vv.w >= 1.0f) ? 1.0f : 0.0f;
                __stcs(reinterpret_cast<float4*>(spikes + off + ko), s);
                vv.x = (s.x != 0.0f) ? 0.0f : vv.x;   // hard reset
                vv.y = (s.y != 0.0f) ? 0.0f : vv.y;
                vv.z = (s.z != 0.0f) ? 0.0f : vv.z;
                vv.w = (s.w != 0.0f) ? 0.0f : vv.w;
                v[k] = vv;
                // Interleaved prefetch for this slot (next t, or next unit
                // t=0), issued AFTER the store into the now-dead xv[k].
                if (more)
                    xv[k] = __ldcs(reinterpret_cast<const float4*>(x + noff + ko));
            }

            // Publish partial sums (STS.128, conflict-free).
            *reinterpret_cast<float4*>(&red[par][ny][4 * cx]) = p;

            __syncthreads();

            // 64 threads reduce 64 n-group partials for 64 c columns; hidden
            // under in-flight prefetch loads. One barrier is safe: the next
            // iteration writes the other parity buffer, and rewriting this
            // one requires these reducer threads to pass the next barrier.
            if (flat < 64) {
                float s = 0.0f;
#pragma unroll
                for (int j = 0; j < 64; j++) s += red[par][j][flat];
                vpool[((size_t)t * B_DIM + b) * C_DIM + ctile * 64 + flat] = s * inv_n;
            }
        }
        __syncthreads();   // unit boundary: red[] parity reuse + v reinit
    }
}

extern "C" void kernel_launch(void* const* d_in, const int* in_sizes, int n_in,
                              void* d_out, int out_size) {
    const float* x     = (const float*)d_in[0];
    const float* decay = (const float*)d_in[1];
    float* spikes = (float*)d_out;
    float* vpool  = (float*)d_out + SPIKES_ELEMS;

    dim3 grid(GRID_X, 1);
    dim3 block(16, 64);    // 16 c-lanes (float4) x 64 n-groups = 1024 threads
    lif_dual_kernel<<<grid, block>>>(x, decay, spikes, vpool);
}